// round 6
// baseline (speedup 1.0000x reference)
#include <cuda_runtime.h>
#include <cstdint>

// ============================================================
// BitFeedForward (Hadamard BitLinear x2) for sm_103 (baseline PTX only:
// cp.async + ldmatrix + mma.sync s8 — no tcgen05, build targets compute_103)
//   out = Wq_dn @ q(FWHT(relu^2( Wq_up @ q(FWHT(x)) )))
//   exact int8 x ternary GEMMs on mma.sync.m16n8k32.s8
// ============================================================

#define MDIM 8192          // B*S tokens
#define HK1  2048          // hidden (layer1 K)
#define HK2  4096          // intermediate (layer2 K)
#define WN   8388608       // elements per weight (4096*2048)

// -------------------- scratch (device globals; no allocs allowed) ---------
__device__ __align__(256) int8_t g_wq_up[WN];
__device__ __align__(256) int8_t g_wq_dn[WN];
__device__ __align__(256) int8_t g_xq[(size_t)MDIM * HK1];
__device__ __align__(256) float  g_h [(size_t)MDIM * HK2];
__device__ __align__(256) int8_t g_hq[(size_t)MDIM * HK2];
__device__ float g_m1[MDIM];
__device__ float g_m2[MDIM];
__device__ float g_ws[2];
__device__ float g_part[512];

// -------------------- PTX helpers (baseline features only) ----------------
#define SWZ(o) ((o) ^ (((o) >> 3) & 0x70))

__device__ __forceinline__ uint32_t smem_u32(const void* p) {
    uint32_t a;
    asm("{ .reg .u64 t; cvta.to.shared.u64 t, %1; cvt.u32.u64 %0, t; }"
        : "=r"(a) : "l"(p));
    return a;
}
__device__ __forceinline__ void cp_async16(uint32_t s, const void* g) {
    asm volatile("cp.async.cg.shared.global [%0], [%1], 16;" :: "r"(s), "l"(g));
}
#define CP_COMMIT() asm volatile("cp.async.commit_group;")
#define CP_WAIT(n)  asm volatile("cp.async.wait_group %0;" :: "n"(n))

__device__ __forceinline__ void ldm4(uint32_t* r, uint32_t addr) {
    asm volatile("ldmatrix.sync.aligned.m8n8.x4.shared.b16 {%0,%1,%2,%3}, [%4];"
                 : "=r"(r[0]), "=r"(r[1]), "=r"(r[2]), "=r"(r[3]) : "r"(addr));
}
__device__ __forceinline__ void mma_s8(int32_t* d, const uint32_t* a,
                                       uint32_t b0, uint32_t b1) {
    asm volatile(
        "mma.sync.aligned.m16n8k32.row.col.s32.s8.s8.s32 "
        "{%0,%1,%2,%3}, {%4,%5,%6,%7}, {%8,%9}, {%0,%1,%2,%3};"
        : "+r"(d[0]), "+r"(d[1]), "+r"(d[2]), "+r"(d[3])
        : "r"(a[0]), "r"(a[1]), "r"(a[2]), "r"(a[3]), "r"(b0), "r"(b1));
}

// -------------------- weight scale: deterministic 2-pass mean|w| ----------
__global__ void wabs_partial(const float* __restrict__ w0,
                             const float* __restrict__ w1,
                             float* __restrict__ part) {
    const float* w = blockIdx.y ? w1 : w0;
    float s = 0.f;
    for (unsigned i = blockIdx.x * 256u + threadIdx.x; i < (unsigned)WN; i += 256u * 256u)
        s += fabsf(w[i]);
    __shared__ float red[256];
    red[threadIdx.x] = s;
    __syncthreads();
    for (int o = 128; o > 0; o >>= 1) {
        if ((int)threadIdx.x < o) red[threadIdx.x] += red[threadIdx.x + o];
        __syncthreads();
    }
    if (threadIdx.x == 0) part[blockIdx.y * 256 + blockIdx.x] = red[0];
}

__global__ void wscale_final(const float* __restrict__ part, float* __restrict__ ws) {
    __shared__ float red[256];
    int t = threadIdx.x;
    red[t] = part[blockIdx.x * 256 + t];
    __syncthreads();
    for (int o = 128; o > 0; o >>= 1) {
        if (t < o) red[t] += red[t + o];
        __syncthreads();
    }
    if (t == 0) ws[blockIdx.x] = fmaxf(red[0] / (float)WN, 1e-5f);
}

// -------------------- ternary weight quantization to int8 (both weights) --
__global__ void wquant_kernel(const float* __restrict__ w0,
                              const float* __restrict__ w1,
                              int8_t* __restrict__ q0,
                              int8_t* __restrict__ q1,
                              const float* __restrict__ wsp) {
    const float* w = blockIdx.y ? w1 : w0;
    int8_t* q = blockIdx.y ? q1 : q0;
    float s = wsp[blockIdx.y];
    unsigned i = blockIdx.x * 256u + threadIdx.x;
    float t = rintf(w[i] / s);                 // IEEE divide, round-half-even (matches jnp)
    t = fminf(fmaxf(t, -1.f), 1.f);
    q[i] = (int8_t)(int)t;
}

// -------------------- FWHT + act_quant kernels (int8 out) -----------------
__global__ void __launch_bounds__(256) fwht_q_2048(const float* __restrict__ X,
                                                   int8_t* __restrict__ Q,
                                                   float* __restrict__ Mv) {
    __shared__ float s[2048];
    __shared__ float red[256];
    __shared__ float sc_s;
    const int row = blockIdx.x;
    const int t = threadIdx.x;

    const float4* xin = (const float4*)(X + (size_t)row * 2048);
    float4* s4 = (float4*)s;
    s4[t] = xin[t];
    s4[t + 256] = xin[t + 256];
    __syncthreads();

    for (int h = 1; h < 2048; h <<= 1) {
#pragma unroll
        for (int k = 0; k < 4; k++) {
            int j = t + k * 256;
            int i = ((j & ~(h - 1)) << 1) | (j & (h - 1));
            float a = s[i], b = s[i + h];
            s[i] = a + b;
            s[i + h] = a - b;
        }
        __syncthreads();
    }

    const float rn = 1.0f / sqrtf(2048.0f);
    float mx = 0.f;
#pragma unroll
    for (int k = 0; k < 8; k++) {
        int i = t + k * 256;
        float v = s[i] * rn;
        s[i] = v;
        mx = fmaxf(mx, fabsf(v));
    }
    red[t] = mx;
    __syncthreads();
    for (int o = 128; o > 0; o >>= 1) {
        if (t < o) red[t] = fmaxf(red[t], red[t + o]);
        __syncthreads();
    }
    if (t == 0) {
        float cm = fmaxf(red[0], 1e-5f);
        sc_s = 127.0f / cm;
        Mv[row] = cm / 127.0f;
    }
    __syncthreads();
    float sc = sc_s;
    int8_t* qrow = Q + (size_t)row * 2048;
#pragma unroll
    for (int k = 0; k < 8; k++) {
        int i = t + k * 256;
        float q = rintf(s[i] * sc);
        q = fminf(fmaxf(q, -127.f), 127.f);
        qrow[i] = (int8_t)(int)q;
    }
}

__global__ void __launch_bounds__(512) fwht_q_4096(const float* __restrict__ X,
                                                   int8_t* __restrict__ Q,
                                                   float* __restrict__ Mv) {
    __shared__ float s[4096];
    __shared__ float red[512];
    __shared__ float sc_s;
    const int row = blockIdx.x;
    const int t = threadIdx.x;

    const float4* xin = (const float4*)(X + (size_t)row * 4096);
    float4* s4 = (float4*)s;
    s4[t] = xin[t];
    s4[t + 512] = xin[t + 512];
    __syncthreads();

    for (int h = 1; h < 4096; h <<= 1) {
#pragma unroll
        for (int k = 0; k < 4; k++) {
            int j = t + k * 512;
            int i = ((j & ~(h - 1)) << 1) | (j & (h - 1));
            float a = s[i], b = s[i + h];
            s[i] = a + b;
            s[i + h] = a - b;
        }
        __syncthreads();
    }

    const float rn = 1.0f / sqrtf(4096.0f);
    float mx = 0.f;
#pragma unroll
    for (int k = 0; k < 8; k++) {
        int i = t + k * 512;
        float v = s[i] * rn;
        s[i] = v;
        mx = fmaxf(mx, fabsf(v));
    }
    red[t] = mx;
    __syncthreads();
    for (int o = 256; o > 0; o >>= 1) {
        if (t < o) red[t] = fmaxf(red[t], red[t + o]);
        __syncthreads();
    }
    if (t == 0) {
        float cm = fmaxf(red[0], 1e-5f);
        sc_s = 127.0f / cm;
        Mv[row] = cm / 127.0f;
    }
    __syncthreads();
    float sc = sc_s;
    int8_t* qrow = Q + (size_t)row * 4096;
#pragma unroll
    for (int k = 0; k < 8; k++) {
        int i = t + k * 512;
        float q = rintf(s[i] * sc);
        q = fminf(fmaxf(q, -127.f), 127.f);
        qrow[i] = (int8_t)(int)q;
    }
}

// -------------------- s8 mma.sync GEMM: D[M,N] = A[M,K] @ B[N,K]^T --------
// Tile: BM=128, BN=128, BK=128 int8, 4-stage cp.async, SW128 swizzle,
// 8 warps (2x4), warp tile 64x32, m16n8k32 s8 MMA, ldmatrix.x4 fragments.
// Epilogue: y = float(acc) * (s_w * m_row);  optionally relu(y)^2.
#define BM 128
#define BN 128
#define BKB 128
#define GSTAGES 4
static constexpr int GEMM_STAGE_BYTES = BM * BKB + BN * BKB;      // 32768
static constexpr int GEMM_SMEM = GSTAGES * GEMM_STAGE_BYTES;      // 131072

template <bool RELUSQ>
__global__ void __launch_bounds__(256, 1) gemm_s8(
    const int8_t* __restrict__ A,
    const int8_t* __restrict__ B,
    const float* __restrict__ rowm,
    const float* __restrict__ wscale,
    float* __restrict__ Cout,
    int KDIM, int NOUT) {
    extern __shared__ __align__(1024) char smem[];
    const int tid = threadIdx.x;
    const int wid = tid >> 5;
    const int lane = tid & 31;
    const uint32_t sb = smem_u32(smem);
    const int m0 = blockIdx.y * BM;
    const int n0 = blockIdx.x * BN;

    const char* Ab = (const char*)(A + (size_t)m0 * KDIM);
    const char* Bb = (const char*)(B + (size_t)n0 * KDIM);
    const int C = KDIM >> 7;                    // chunks of 128 int8

    // per-thread cp.async pattern: 4 chunks A + 4 chunks B per stage
    const int ldr = tid >> 3;                   // 0..31 (base row)
    const int ldc = (tid & 7) * 16;             // 16B chunk within row

    auto load_stage = [&](int c, int st) {
        uint32_t sA = sb + (uint32_t)st * GEMM_STAGE_BYTES;
        uint32_t sB = sA + BM * BKB;
        const char* Ag = Ab + (size_t)c * BKB;
        const char* Bg = Bb + (size_t)c * BKB;
#pragma unroll
        for (int i = 0; i < 4; i++) {
            int r = ldr + i * 32;
            uint32_t so = (uint32_t)(r * BKB + ldc);
            cp_async16(sA + SWZ(so), Ag + (size_t)r * KDIM + ldc);
        }
#pragma unroll
        for (int i = 0; i < 4; i++) {
            int r = ldr + i * 32;
            uint32_t so = (uint32_t)(r * BKB + ldc);
            cp_async16(sB + SWZ(so), Bg + (size_t)r * KDIM + ldc);
        }
    };

    // prologue: 3 stages in flight
    load_stage(0, 0); CP_COMMIT();
    load_stage(1, 1); CP_COMMIT();
    load_stage(2, 2); CP_COMMIT();

    // warp tiling: 2 (M) x 4 (N) warps, warp tile 64x32
    const int wm = (wid & 1) * 64;
    const int wn = (wid >> 1) * 32;
    // ldmatrix per-lane quadrant addressing
    const int q = lane >> 3;
    const int row_off = (q & 1) * 8 + (lane & 7);   // 0..15
    const int kb_off = (q >> 1) * 16;               // 0 or 16

    int32_t acc[4][4][4];
#pragma unroll
    for (int mt = 0; mt < 4; mt++)
#pragma unroll
        for (int nt = 0; nt < 4; nt++)
#pragma unroll
            for (int r = 0; r < 4; r++) acc[mt][nt][r] = 0;

    for (int c = 0; c < C; c++) {
        CP_WAIT(2);
        __syncthreads();
        if (c + 3 < C) load_stage(c + 3, (c + 3) & 3);
        CP_COMMIT();                     // uniform group accounting (empty ok)

        uint32_t sA = sb + (uint32_t)(c & 3) * GEMM_STAGE_BYTES;
        uint32_t sB = sA + BM * BKB;
#pragma unroll
        for (int ks = 0; ks < 4; ks++) {
            uint32_t afr[4][4];
#pragma unroll
            for (int mt = 0; mt < 4; mt++) {
                uint32_t off = (uint32_t)((wm + mt * 16 + row_off) * BKB +
                                          ks * 32 + kb_off);
                ldm4(afr[mt], sA + SWZ(off));
            }
            uint32_t bfr[2][4];
#pragma unroll
            for (int nh = 0; nh < 2; nh++) {
                uint32_t off = (uint32_t)((wn + nh * 16 + row_off) * BKB +
                                          ks * 32 + kb_off);
                ldm4(bfr[nh], sB + SWZ(off));
            }
#pragma unroll
            for (int mt = 0; mt < 4; mt++)
#pragma unroll
                for (int nt = 0; nt < 4; nt++) {
                    int nh = nt >> 1, sel = nt & 1;
                    mma_s8(acc[mt][nt], afr[mt], bfr[nh][sel], bfr[nh][sel + 2]);
                }
        }
        __syncthreads();                 // compute done before stage reuse
    }

    // ---- epilogue ----
    const float wsv = *wscale;
    const int lr = lane >> 2;            // 0..7
    const int lc = (lane & 3) * 2;
#pragma unroll
    for (int mt = 0; mt < 4; mt++) {
        int r0 = m0 + wm + mt * 16 + lr;
        int r1 = r0 + 8;
        float al0 = wsv * rowm[r0];
        float al1 = wsv * rowm[r1];
        float* o0 = Cout + (size_t)r0 * NOUT + n0 + wn;
        float* o1 = Cout + (size_t)r1 * NOUT + n0 + wn;
#pragma unroll
        for (int nt = 0; nt < 4; nt++) {
            int colb = nt * 8 + lc;
            float y0 = (float)acc[mt][nt][0] * al0;
            float y1 = (float)acc[mt][nt][1] * al0;
            float y2 = (float)acc[mt][nt][2] * al1;
            float y3 = (float)acc[mt][nt][3] * al1;
            if (RELUSQ) {
                y0 = y0 > 0.f ? y0 * y0 : 0.f;
                y1 = y1 > 0.f ? y1 * y1 : 0.f;
                y2 = y2 > 0.f ? y2 * y2 : 0.f;
                y3 = y3 > 0.f ? y3 * y3 : 0.f;
            }
            *(float2*)(o0 + colb) = make_float2(y0, y1);
            *(float2*)(o1 + colb) = make_float2(y2, y3);
        }
    }
}

// -------------------- host entry ------------------------------------------
extern "C" void kernel_launch(void* const* d_in, const int* in_sizes, int n_in,
                              void* d_out, int out_size) {
    const float* x  = (const float*)d_in[0];   // [4,2048,2048]
    const float* wu = (const float*)d_in[1];   // [4096,2048]
    const float* wd = (const float*)d_in[2];   // [2048,4096]
    float* out = (float*)d_out;                // [4,2048,2048]

    void *p_wqu, *p_wqd, *p_xq, *p_h, *p_hq, *p_m1, *p_m2, *p_ws, *p_part;
    cudaGetSymbolAddress(&p_wqu, g_wq_up);
    cudaGetSymbolAddress(&p_wqd, g_wq_dn);
    cudaGetSymbolAddress(&p_xq,  g_xq);
    cudaGetSymbolAddress(&p_h,   g_h);
    cudaGetSymbolAddress(&p_hq,  g_hq);
    cudaGetSymbolAddress(&p_m1,  g_m1);
    cudaGetSymbolAddress(&p_m2,  g_m2);
    cudaGetSymbolAddress(&p_ws,  g_ws);
    cudaGetSymbolAddress(&p_part, g_part);

    cudaFuncSetAttribute(gemm_s8<true>,
                         cudaFuncAttributeMaxDynamicSharedMemorySize, GEMM_SMEM);
    cudaFuncSetAttribute(gemm_s8<false>,
                         cudaFuncAttributeMaxDynamicSharedMemorySize, GEMM_SMEM);

    // 1) weight scales (mean|w|, deterministic two-pass)
    wabs_partial<<<dim3(256, 2), 256>>>(wu, wd, (float*)p_part);
    wscale_final<<<2, 256>>>((const float*)p_part, (float*)p_ws);

    // 2) ternary-quantize both weights into int8 (single launch, grid.y=2)
    wquant_kernel<<<dim3(WN / 256, 2), 256>>>(wu, wd,
        (int8_t*)p_wqu, (int8_t*)p_wqd, (const float*)p_ws);

    // 3) FWHT(2048) + act quant -> int8
    fwht_q_2048<<<MDIM, 256>>>(x, (int8_t*)p_xq, (float*)p_m1);

    // 4) GEMM1 (8192x4096x2048) + relu^2 epilogue -> g_h (f32)
    gemm_s8<true><<<dim3(HK2 / BN, MDIM / BM), 256, GEMM_SMEM>>>(
        (const int8_t*)p_xq, (const int8_t*)p_wqu,
        (const float*)p_m1, (const float*)p_ws,
        (float*)p_h, HK1, HK2);

    // 5) FWHT(4096) + act quant -> int8
    fwht_q_4096<<<MDIM, 512>>>((const float*)p_h, (int8_t*)p_hq, (float*)p_m2);

    // 6) GEMM2 (8192x2048x4096) -> out
    gemm_s8<false><<<dim3(HK1 / BN, MDIM / BM), 256, GEMM_SMEM>>>(
        (const int8_t*)p_hq, (const int8_t*)p_wqd,
        (const float*)p_m2, (const float*)p_ws + 1,
        out, HK2, HK1);
}

// round 7
// speedup vs baseline: 1.1072x; 1.1072x over previous
#include <cuda_runtime.h>
#include <cstdint>

// ============================================================
// BitFeedForward (Hadamard BitLinear x2) for sm_103 (baseline PTX only:
// cp.async + ldmatrix + mma.sync s8 — no tcgen05 in this toolchain)
//   out = Wq_dn @ q(FWHT(relu^2( Wq_up @ q(FWHT(x)) )))
// R7: GEMM 3-stage smem -> 2 CTAs/SM (latency-hiding test);
//     FWHT redone as register radix-8 + warp shuffles (3-4 smem stages only)
// ============================================================

#define MDIM 8192          // B*S tokens
#define HK1  2048          // hidden (layer1 K)
#define HK2  4096          // intermediate (layer2 K)
#define WN   8388608       // elements per weight (4096*2048)

// -------------------- scratch (device globals; no allocs allowed) ---------
__device__ __align__(256) int8_t g_wq_up[WN];
__device__ __align__(256) int8_t g_wq_dn[WN];
__device__ __align__(256) int8_t g_xq[(size_t)MDIM * HK1];
__device__ __align__(256) float  g_h [(size_t)MDIM * HK2];
__device__ __align__(256) int8_t g_hq[(size_t)MDIM * HK2];
__device__ float g_m1[MDIM];
__device__ float g_m2[MDIM];
__device__ float g_ws[2];
__device__ float g_part[512];

// -------------------- PTX helpers (baseline features only) ----------------
#define SWZ(o) ((o) ^ (((o) >> 3) & 0x70))

__device__ __forceinline__ uint32_t smem_u32(const void* p) {
    uint32_t a;
    asm("{ .reg .u64 t; cvta.to.shared.u64 t, %1; cvt.u32.u64 %0, t; }"
        : "=r"(a) : "l"(p));
    return a;
}
__device__ __forceinline__ void cp_async16(uint32_t s, const void* g) {
    asm volatile("cp.async.cg.shared.global [%0], [%1], 16;" :: "r"(s), "l"(g));
}
#define CP_COMMIT() asm volatile("cp.async.commit_group;")
#define CP_WAIT(n)  asm volatile("cp.async.wait_group %0;" :: "n"(n))

__device__ __forceinline__ void ldm4(uint32_t* r, uint32_t addr) {
    asm volatile("ldmatrix.sync.aligned.m8n8.x4.shared.b16 {%0,%1,%2,%3}, [%4];"
                 : "=r"(r[0]), "=r"(r[1]), "=r"(r[2]), "=r"(r[3]) : "r"(addr));
}
__device__ __forceinline__ void mma_s8(int32_t* d, const uint32_t* a,
                                       uint32_t b0, uint32_t b1) {
    asm volatile(
        "mma.sync.aligned.m16n8k32.row.col.s32.s8.s8.s32 "
        "{%0,%1,%2,%3}, {%4,%5,%6,%7}, {%8,%9}, {%0,%1,%2,%3};"
        : "+r"(d[0]), "+r"(d[1]), "+r"(d[2]), "+r"(d[3])
        : "r"(a[0]), "r"(a[1]), "r"(a[2]), "r"(a[3]), "r"(b0), "r"(b1));
}

// -------------------- weight scale: deterministic 2-pass mean|w| ----------
__global__ void wabs_partial(const float* __restrict__ w0,
                             const float* __restrict__ w1,
                             float* __restrict__ part) {
    const float* w = blockIdx.y ? w1 : w0;
    float s = 0.f;
    for (unsigned i = blockIdx.x * 256u + threadIdx.x; i < (unsigned)WN; i += 256u * 256u)
        s += fabsf(w[i]);
    __shared__ float red[256];
    red[threadIdx.x] = s;
    __syncthreads();
    for (int o = 128; o > 0; o >>= 1) {
        if ((int)threadIdx.x < o) red[threadIdx.x] += red[threadIdx.x + o];
        __syncthreads();
    }
    if (threadIdx.x == 0) part[blockIdx.y * 256 + blockIdx.x] = red[0];
}

__global__ void wscale_final(const float* __restrict__ part, float* __restrict__ ws) {
    __shared__ float red[256];
    int t = threadIdx.x;
    red[t] = part[blockIdx.x * 256 + t];
    __syncthreads();
    for (int o = 128; o > 0; o >>= 1) {
        if (t < o) red[t] += red[t + o];
        __syncthreads();
    }
    if (t == 0) ws[blockIdx.x] = fmaxf(red[0] / (float)WN, 1e-5f);
}

// -------------------- ternary weight quantization to int8 (both weights) --
__global__ void wquant_kernel(const float* __restrict__ w0,
                              const float* __restrict__ w1,
                              int8_t* __restrict__ q0,
                              int8_t* __restrict__ q1,
                              const float* __restrict__ wsp) {
    const float* w = blockIdx.y ? w1 : w0;
    int8_t* q = blockIdx.y ? q1 : q0;
    float s = wsp[blockIdx.y];
    unsigned i = blockIdx.x * 256u + threadIdx.x;
    float t = rintf(w[i] / s);                 // IEEE divide, round-half-even (matches jnp)
    t = fminf(fmaxf(t, -1.f), 1.f);
    q[i] = (int8_t)(int)t;
}

// -------------------- FWHT + act_quant: register radix-8 + shuffles -------
// Each thread owns 8 consecutive elements. Stages:
//   h=1,2,4     : in registers
//   h=8..128    : warp shuffles (partner lane = lane ^ (h/8))
//   h>=256      : cross-warp via padded smem exchange (3 or 4 stages)
// FP op order identical to the simple smem version -> bit-identical output.
template <int NROW, int T>
__global__ void __launch_bounds__(T) fwht_q(const float* __restrict__ X,
                                            int8_t* __restrict__ Q,
                                            float* __restrict__ Mv) {
    __shared__ float sx[T * 9 + 8];
    __shared__ float wmax[T / 32];
    __shared__ float scs;
    const int row = blockIdx.x;
    const int t = threadIdx.x;
    const int lane = t & 31;
    const int wid = t >> 5;

    float v[8];
    {
        const float4* xin = (const float4*)(X + (size_t)row * NROW) + t * 2;
        float4 p0 = xin[0], p1 = xin[1];
        v[0] = p0.x; v[1] = p0.y; v[2] = p0.z; v[3] = p0.w;
        v[4] = p1.x; v[5] = p1.y; v[6] = p1.z; v[7] = p1.w;
    }

    // in-register stages h = 1, 2, 4
#pragma unroll
    for (int h = 1; h <= 4; h <<= 1) {
#pragma unroll
        for (int r = 0; r < 8; r++) {
            if (!(r & h)) {
                float a = v[r], b = v[r + h];
                v[r] = a + b;
                v[r + h] = a - b;
            }
        }
    }

    // warp-shuffle stages h = 8..128 (d = 1..16)
#pragma unroll
    for (int d = 1; d <= 16; d <<= 1) {
        bool up = (lane & d) != 0;
#pragma unroll
        for (int r = 0; r < 8; r++) {
            float o = __shfl_xor_sync(0xFFFFFFFFu, v[r], d);
            v[r] = up ? (o - v[r]) : (v[r] + o);
        }
    }

    // cross-warp stages via smem (d = 32 .. T/2)
    const int base = t * 8 + (t >> 2) * 4;      // 16B pad per 4 threads: conflict-free
#pragma unroll
    for (int d = 32; d <= T / 2; d <<= 1) {
        *(float4*)(sx + base)     = make_float4(v[0], v[1], v[2], v[3]);
        *(float4*)(sx + base + 4) = make_float4(v[4], v[5], v[6], v[7]);
        __syncthreads();
        int pt = t ^ d;
        int pb = pt * 8 + (pt >> 2) * 4;
        float4 u0 = *(float4*)(sx + pb);
        float4 u1 = *(float4*)(sx + pb + 4);
        bool up = (t & d) != 0;
        v[0] = up ? (u0.x - v[0]) : (v[0] + u0.x);
        v[1] = up ? (u0.y - v[1]) : (v[1] + u0.y);
        v[2] = up ? (u0.z - v[2]) : (v[2] + u0.z);
        v[3] = up ? (u0.w - v[3]) : (v[3] + u0.w);
        v[4] = up ? (u1.x - v[4]) : (v[4] + u1.x);
        v[5] = up ? (u1.y - v[5]) : (v[5] + u1.y);
        v[6] = up ? (u1.z - v[6]) : (v[6] + u1.z);
        v[7] = up ? (u1.w - v[7]) : (v[7] + u1.w);
        __syncthreads();
    }

    // normalize + row absmax
    const float rn = 1.0f / sqrtf((float)NROW);
    float mx = 0.f;
#pragma unroll
    for (int r = 0; r < 8; r++) {
        v[r] *= rn;
        mx = fmaxf(mx, fabsf(v[r]));
    }
#pragma unroll
    for (int o = 16; o > 0; o >>= 1)
        mx = fmaxf(mx, __shfl_xor_sync(0xFFFFFFFFu, mx, o));
    if (lane == 0) wmax[wid] = mx;
    __syncthreads();
    if (t == 0) {
        float m = wmax[0];
#pragma unroll
        for (int i = 1; i < T / 32; i++) m = fmaxf(m, wmax[i]);
        m = fmaxf(m, 1e-5f);
        scs = 127.0f / m;
        Mv[row] = m / 127.0f;
    }
    __syncthreads();
    const float sc = scs;

    // quantize to int8, pack 8 bytes, single 8B store
    int b[8];
#pragma unroll
    for (int r = 0; r < 8; r++) {
        float q = rintf(v[r] * sc);
        q = fminf(fmaxf(q, -127.f), 127.f);
        b[r] = (int)q;
    }
    uint32_t lo = (uint32_t)(b[0] & 0xFF) | ((uint32_t)(b[1] & 0xFF) << 8) |
                  ((uint32_t)(b[2] & 0xFF) << 16) | ((uint32_t)(b[3] & 0xFF) << 24);
    uint32_t hi = (uint32_t)(b[4] & 0xFF) | ((uint32_t)(b[5] & 0xFF) << 8) |
                  ((uint32_t)(b[6] & 0xFF) << 16) | ((uint32_t)(b[7] & 0xFF) << 24);
    uint2 st; st.x = lo; st.y = hi;
    ((uint2*)(Q + (size_t)row * NROW))[t] = st;
}

// -------------------- s8 mma.sync GEMM: D[M,N] = A[M,K] @ B[N,K]^T --------
// Tile: BM=128, BN=128, BK=128 int8, 3-stage cp.async, SW128 swizzle,
// 8 warps (2x4), warp tile 64x32, m16n8k32 s8 MMA, ldmatrix.x4 fragments.
// 3 stages (96KB smem) -> 2 CTAs/SM for latency hiding.
// Epilogue: y = float(acc) * (s_w * m_row);  optionally relu(y)^2.
#define BM 128
#define BN 128
#define BKB 128
static constexpr int GEMM_STAGE_BYTES = BM * BKB + BN * BKB;      // 32768
static constexpr int GEMM_SMEM = 3 * GEMM_STAGE_BYTES;            // 98304

template <bool RELUSQ>
__global__ void __launch_bounds__(256, 2) gemm_s8(
    const int8_t* __restrict__ A,
    const int8_t* __restrict__ B,
    const float* __restrict__ rowm,
    const float* __restrict__ wscale,
    float* __restrict__ Cout,
    int KDIM, int NOUT) {
    extern __shared__ __align__(1024) char smem[];
    const int tid = threadIdx.x;
    const int wid = tid >> 5;
    const int lane = tid & 31;
    const uint32_t sb = smem_u32(smem);
    const int m0 = blockIdx.y * BM;
    const int n0 = blockIdx.x * BN;

    const char* Ab = (const char*)(A + (size_t)m0 * KDIM);
    const char* Bb = (const char*)(B + (size_t)n0 * KDIM);
    const int C = KDIM >> 7;                    // chunks of 128 int8

    // per-thread cp.async pattern: 4 chunks A + 4 chunks B per stage
    const int ldr = tid >> 3;                   // 0..31 (base row)
    const int ldc = (tid & 7) * 16;             // 16B chunk within row

    auto load_stage = [&](int c, int st) {
        uint32_t sA = sb + (uint32_t)st * GEMM_STAGE_BYTES;
        uint32_t sB = sA + BM * BKB;
        const char* Ag = Ab + (size_t)c * BKB;
        const char* Bg = Bb + (size_t)c * BKB;
#pragma unroll
        for (int i = 0; i < 4; i++) {
            int r = ldr + i * 32;
            uint32_t so = (uint32_t)(r * BKB + ldc);
            cp_async16(sA + SWZ(so), Ag + (size_t)r * KDIM + ldc);
        }
#pragma unroll
        for (int i = 0; i < 4; i++) {
            int r = ldr + i * 32;
            uint32_t so = (uint32_t)(r * BKB + ldc);
            cp_async16(sB + SWZ(so), Bg + (size_t)r * KDIM + ldc);
        }
    };

    // prologue: 2 stages in flight
    load_stage(0, 0); CP_COMMIT();
    load_stage(1, 1); CP_COMMIT();

    // warp tiling: 2 (M) x 4 (N) warps, warp tile 64x32
    const int wm = (wid & 1) * 64;
    const int wn = (wid >> 1) * 32;
    // ldmatrix per-lane quadrant addressing
    const int q = lane >> 3;
    const int row_off = (q & 1) * 8 + (lane & 7);   // 0..15
    const int kb_off = (q >> 1) * 16;               // 0 or 16

    int32_t acc[4][4][4];
#pragma unroll
    for (int mt = 0; mt < 4; mt++)
#pragma unroll
        for (int nt = 0; nt < 4; nt++)
#pragma unroll
            for (int r = 0; r < 4; r++) acc[mt][nt][r] = 0;

    int stc = 0;                                   // stage of chunk c
    for (int c = 0; c < C; c++) {
        CP_WAIT(1);
        __syncthreads();
        // load chunk c+2 into the stage freed by chunk c-1 (barrier above
        // plus the trailing barrier of iter c-1 make it safe)
        int st2 = stc + 2; if (st2 >= 3) st2 -= 3;
        if (c + 2 < C) load_stage(c + 2, st2);
        CP_COMMIT();                               // uniform group accounting

        uint32_t sA = sb + (uint32_t)stc * GEMM_STAGE_BYTES;
        uint32_t sB = sA + BM * BKB;
#pragma unroll
        for (int ks = 0; ks < 4; ks++) {
            uint32_t afr[4][4];
#pragma unroll
            for (int mt = 0; mt < 4; mt++) {
                uint32_t off = (uint32_t)((wm + mt * 16 + row_off) * BKB +
                                          ks * 32 + kb_off);
                ldm4(afr[mt], sA + SWZ(off));
            }
            uint32_t bfr[2][4];
#pragma unroll
            for (int nh = 0; nh < 2; nh++) {
                uint32_t off = (uint32_t)((wn + nh * 16 + row_off) * BKB +
                                          ks * 32 + kb_off);
                ldm4(bfr[nh], sB + SWZ(off));
            }
#pragma unroll
            for (int mt = 0; mt < 4; mt++)
#pragma unroll
                for (int nt = 0; nt < 4; nt++) {
                    int nh = nt >> 1, sel = nt & 1;
                    mma_s8(acc[mt][nt], afr[mt], bfr[nh][sel], bfr[nh][sel + 2]);
                }
        }
        __syncthreads();                 // compute done before stage reuse
        if (++stc == 3) stc = 0;
    }

    // ---- epilogue ----
    const float wsv = *wscale;
    const int lr = lane >> 2;            // 0..7
    const int lc = (lane & 3) * 2;
#pragma unroll
    for (int mt = 0; mt < 4; mt++) {
        int r0 = m0 + wm + mt * 16 + lr;
        int r1 = r0 + 8;
        float al0 = wsv * rowm[r0];
        float al1 = wsv * rowm[r1];
        float* o0 = Cout + (size_t)r0 * NOUT + n0 + wn;
        float* o1 = Cout + (size_t)r1 * NOUT + n0 + wn;
#pragma unroll
        for (int nt = 0; nt < 4; nt++) {
            int colb = nt * 8 + lc;
            float y0 = (float)acc[mt][nt][0] * al0;
            float y1 = (float)acc[mt][nt][1] * al0;
            float y2 = (float)acc[mt][nt][2] * al1;
            float y3 = (float)acc[mt][nt][3] * al1;
            if (RELUSQ) {
                y0 = y0 > 0.f ? y0 * y0 : 0.f;
                y1 = y1 > 0.f ? y1 * y1 : 0.f;
                y2 = y2 > 0.f ? y2 * y2 : 0.f;
                y3 = y3 > 0.f ? y3 * y3 : 0.f;
            }
            *(float2*)(o0 + colb) = make_float2(y0, y1);
            *(float2*)(o1 + colb) = make_float2(y2, y3);
        }
    }
}

// -------------------- host entry ------------------------------------------
extern "C" void kernel_launch(void* const* d_in, const int* in_sizes, int n_in,
                              void* d_out, int out_size) {
    const float* x  = (const float*)d_in[0];   // [4,2048,2048]
    const float* wu = (const float*)d_in[1];   // [4096,2048]
    const float* wd = (const float*)d_in[2];   // [2048,4096]
    float* out = (float*)d_out;                // [4,2048,2048]

    void *p_wqu, *p_wqd, *p_xq, *p_h, *p_hq, *p_m1, *p_m2, *p_ws, *p_part;
    cudaGetSymbolAddress(&p_wqu, g_wq_up);
    cudaGetSymbolAddress(&p_wqd, g_wq_dn);
    cudaGetSymbolAddress(&p_xq,  g_xq);
    cudaGetSymbolAddress(&p_h,   g_h);
    cudaGetSymbolAddress(&p_hq,  g_hq);
    cudaGetSymbolAddress(&p_m1,  g_m1);
    cudaGetSymbolAddress(&p_m2,  g_m2);
    cudaGetSymbolAddress(&p_ws,  g_ws);
    cudaGetSymbolAddress(&p_part, g_part);

    cudaFuncSetAttribute(gemm_s8<true>,
                         cudaFuncAttributeMaxDynamicSharedMemorySize, GEMM_SMEM);
    cudaFuncSetAttribute(gemm_s8<false>,
                         cudaFuncAttributeMaxDynamicSharedMemorySize, GEMM_SMEM);

    // 1) weight scales (mean|w|, deterministic two-pass)
    wabs_partial<<<dim3(256, 2), 256>>>(wu, wd, (float*)p_part);
    wscale_final<<<2, 256>>>((const float*)p_part, (float*)p_ws);

    // 2) ternary-quantize both weights into int8 (single launch, grid.y=2)
    wquant_kernel<<<dim3(WN / 256, 2), 256>>>(wu, wd,
        (int8_t*)p_wqu, (int8_t*)p_wqd, (const float*)p_ws);

    // 3) FWHT(2048) + act quant -> int8
    fwht_q<HK1, 256><<<MDIM, 256>>>(x, (int8_t*)p_xq, (float*)p_m1);

    // 4) GEMM1 (8192x4096x2048) + relu^2 epilogue -> g_h (f32)
    gemm_s8<true><<<dim3(HK2 / BN, MDIM / BM), 256, GEMM_SMEM>>>(
        (const int8_t*)p_xq, (const int8_t*)p_wqu,
        (const float*)p_m1, (const float*)p_ws,
        (float*)p_h, HK1, HK2);

    // 5) FWHT(4096) + act quant -> int8
    fwht_q<HK2, 512><<<MDIM, 512>>>((const float*)p_h, (int8_t*)p_hq, (float*)p_m2);

    // 6) GEMM2 (8192x2048x4096) -> out
    gemm_s8<false><<<dim3(HK1 / BN, MDIM / BM), 256, GEMM_SMEM>>>(
        (const int8_t*)p_hq, (const int8_t*)p_wqd,
        (const float*)p_m2, (const float*)p_ws + 1,
        out, HK2, HK1);
}

// round 8
// speedup vs baseline: 2.4464x; 2.2096x over previous
#include <cuda_runtime.h>
#include <cuda_bf16.h>
#include <cstdint>

// ============================================================
// BitFeedForward (Hadamard BitLinear x2) for sm_103
// R8: GEMMs converted s8->bf16 HMMA (mma.sync.m16n8k16.f32.bf16.bf16.f32).
//     Theory: s8 mma.sync is dp4a-emulated (~256 MAC/cyc/SM measured);
//     HMMA is native fallback on sm_103 (~1024 MAC/cyc/SM expected).
//     Integer math exact in bf16 (|act|<=127, ternary weights, f32 acc).
// ============================================================

#define MDIM 8192          // B*S tokens
#define HK1  2048          // hidden (layer1 K)
#define HK2  4096          // intermediate (layer2 K)
#define WN   8388608       // elements per weight (4096*2048)

// -------------------- scratch (device globals; no allocs allowed) ---------
__device__ __align__(256) __nv_bfloat16 g_wq_up[WN];
__device__ __align__(256) __nv_bfloat16 g_wq_dn[WN];
__device__ __align__(256) __nv_bfloat16 g_xq[(size_t)MDIM * HK1];
__device__ __align__(256) float         g_h [(size_t)MDIM * HK2];
__device__ __align__(256) __nv_bfloat16 g_hq[(size_t)MDIM * HK2];
__device__ float g_m1[MDIM];
__device__ float g_m2[MDIM];
__device__ float g_ws[2];
__device__ float g_part[512];

// -------------------- PTX helpers ----------------------------------------
#define SWZ(o) ((o) ^ (((o) >> 3) & 0x70))

__device__ __forceinline__ uint32_t smem_u32(const void* p) {
    uint32_t a;
    asm("{ .reg .u64 t; cvta.to.shared.u64 t, %1; cvt.u32.u64 %0, t; }"
        : "=r"(a) : "l"(p));
    return a;
}
__device__ __forceinline__ void cp_async16(uint32_t s, const void* g) {
    asm volatile("cp.async.cg.shared.global [%0], [%1], 16;" :: "r"(s), "l"(g));
}
#define CP_COMMIT() asm volatile("cp.async.commit_group;")
#define CP_WAIT(n)  asm volatile("cp.async.wait_group %0;" :: "n"(n))

__device__ __forceinline__ void ldm4(uint32_t* r, uint32_t addr) {
    asm volatile("ldmatrix.sync.aligned.m8n8.x4.shared.b16 {%0,%1,%2,%3}, [%4];"
                 : "=r"(r[0]), "=r"(r[1]), "=r"(r[2]), "=r"(r[3]) : "r"(addr));
}
__device__ __forceinline__ void mma_bf16(float* d, const uint32_t* a,
                                         uint32_t b0, uint32_t b1) {
    asm volatile(
        "mma.sync.aligned.m16n8k16.row.col.f32.bf16.bf16.f32 "
        "{%0,%1,%2,%3}, {%4,%5,%6,%7}, {%8,%9}, {%0,%1,%2,%3};"
        : "+f"(d[0]), "+f"(d[1]), "+f"(d[2]), "+f"(d[3])
        : "r"(a[0]), "r"(a[1]), "r"(a[2]), "r"(a[3]), "r"(b0), "r"(b1));
}

// -------------------- weight scale: deterministic 2-pass mean|w| ----------
__global__ void wabs_partial(const float* __restrict__ w0,
                             const float* __restrict__ w1,
                             float* __restrict__ part) {
    const float* w = blockIdx.y ? w1 : w0;
    float s = 0.f;
    for (unsigned i = blockIdx.x * 256u + threadIdx.x; i < (unsigned)WN; i += 256u * 256u)
        s += fabsf(w[i]);
    __shared__ float red[256];
    red[threadIdx.x] = s;
    __syncthreads();
    for (int o = 128; o > 0; o >>= 1) {
        if ((int)threadIdx.x < o) red[threadIdx.x] += red[threadIdx.x + o];
        __syncthreads();
    }
    if (threadIdx.x == 0) part[blockIdx.y * 256 + blockIdx.x] = red[0];
}

__global__ void wscale_final(const float* __restrict__ part, float* __restrict__ ws) {
    __shared__ float red[256];
    int t = threadIdx.x;
    red[t] = part[blockIdx.x * 256 + t];
    __syncthreads();
    for (int o = 128; o > 0; o >>= 1) {
        if (t < o) red[t] += red[t + o];
        __syncthreads();
    }
    if (t == 0) ws[blockIdx.x] = fmaxf(red[0] / (float)WN, 1e-5f);
}

// -------------------- ternary weight quantization to bf16 (both weights) --
__global__ void wquant_kernel(const float* __restrict__ w0,
                              const float* __restrict__ w1,
                              __nv_bfloat16* __restrict__ q0,
                              __nv_bfloat16* __restrict__ q1,
                              const float* __restrict__ wsp) {
    const float* w = blockIdx.y ? w1 : w0;
    __nv_bfloat16* q = blockIdx.y ? q1 : q0;
    float s = wsp[blockIdx.y];
    unsigned i = blockIdx.x * 256u + threadIdx.x;
    float t = rintf(w[i] / s);                 // IEEE divide, round-half-even (matches jnp)
    t = fminf(fmaxf(t, -1.f), 1.f);
    q[i] = __float2bfloat16(t);                // {-1,0,1}: exact
}

// -------------------- FWHT + act_quant: register radix-8 + shuffles -------
// Each thread owns 8 consecutive elements. Stages:
//   h=1,2,4     : in registers
//   h=8..128    : warp shuffles (partner lane = lane ^ (h/8))
//   h>=256      : cross-warp via padded smem exchange (3 or 4 stages)
// Output: bf16 quantized ints (|q|<=127, exact in bf16).
template <int NROW, int T>
__global__ void __launch_bounds__(T) fwht_q(const float* __restrict__ X,
                                            __nv_bfloat16* __restrict__ Q,
                                            float* __restrict__ Mv) {
    __shared__ float sx[T * 9 + 8];
    __shared__ float wmax[T / 32];
    __shared__ float scs;
    const int row = blockIdx.x;
    const int t = threadIdx.x;
    const int lane = t & 31;
    const int wid = t >> 5;

    float v[8];
    {
        const float4* xin = (const float4*)(X + (size_t)row * NROW) + t * 2;
        float4 p0 = xin[0], p1 = xin[1];
        v[0] = p0.x; v[1] = p0.y; v[2] = p0.z; v[3] = p0.w;
        v[4] = p1.x; v[5] = p1.y; v[6] = p1.z; v[7] = p1.w;
    }

    // in-register stages h = 1, 2, 4
#pragma unroll
    for (int h = 1; h <= 4; h <<= 1) {
#pragma unroll
        for (int r = 0; r < 8; r++) {
            if (!(r & h)) {
                float a = v[r], b = v[r + h];
                v[r] = a + b;
                v[r + h] = a - b;
            }
        }
    }

    // warp-shuffle stages h = 8..128 (d = 1..16)
#pragma unroll
    for (int d = 1; d <= 16; d <<= 1) {
        bool up = (lane & d) != 0;
#pragma unroll
        for (int r = 0; r < 8; r++) {
            float o = __shfl_xor_sync(0xFFFFFFFFu, v[r], d);
            v[r] = up ? (o - v[r]) : (v[r] + o);
        }
    }

    // cross-warp stages via smem (d = 32 .. T/2)
    const int base = t * 8 + (t >> 2) * 4;      // 16B pad per 4 threads: conflict-free
#pragma unroll
    for (int d = 32; d <= T / 2; d <<= 1) {
        *(float4*)(sx + base)     = make_float4(v[0], v[1], v[2], v[3]);
        *(float4*)(sx + base + 4) = make_float4(v[4], v[5], v[6], v[7]);
        __syncthreads();
        int pt = t ^ d;
        int pb = pt * 8 + (pt >> 2) * 4;
        float4 u0 = *(float4*)(sx + pb);
        float4 u1 = *(float4*)(sx + pb + 4);
        bool up = (t & d) != 0;
        v[0] = up ? (u0.x - v[0]) : (v[0] + u0.x);
        v[1] = up ? (u0.y - v[1]) : (v[1] + u0.y);
        v[2] = up ? (u0.z - v[2]) : (v[2] + u0.z);
        v[3] = up ? (u0.w - v[3]) : (v[3] + u0.w);
        v[4] = up ? (u1.x - v[4]) : (v[4] + u1.x);
        v[5] = up ? (u1.y - v[5]) : (v[5] + u1.y);
        v[6] = up ? (u1.z - v[6]) : (v[6] + u1.z);
        v[7] = up ? (u1.w - v[7]) : (v[7] + u1.w);
        __syncthreads();
    }

    // normalize + row absmax
    const float rn = 1.0f / sqrtf((float)NROW);
    float mx = 0.f;
#pragma unroll
    for (int r = 0; r < 8; r++) {
        v[r] *= rn;
        mx = fmaxf(mx, fabsf(v[r]));
    }
#pragma unroll
    for (int o = 16; o > 0; o >>= 1)
        mx = fmaxf(mx, __shfl_xor_sync(0xFFFFFFFFu, mx, o));
    if (lane == 0) wmax[wid] = mx;
    __syncthreads();
    if (t == 0) {
        float m = wmax[0];
#pragma unroll
        for (int i = 1; i < T / 32; i++) m = fmaxf(m, wmax[i]);
        m = fmaxf(m, 1e-5f);
        scs = 127.0f / m;
        Mv[row] = m / 127.0f;
    }
    __syncthreads();
    const float sc = scs;

    // quantize, convert to bf16 (exact for ints <=127), pack 8 -> 16B store
    uint32_t w[4];
#pragma unroll
    for (int r = 0; r < 4; r++) {
        float q0 = rintf(v[2 * r] * sc);
        float q1 = rintf(v[2 * r + 1] * sc);
        q0 = fminf(fmaxf(q0, -127.f), 127.f);
        q1 = fminf(fmaxf(q1, -127.f), 127.f);
        uint32_t lo = (uint32_t)__bfloat16_as_ushort(__float2bfloat16(q0));
        uint32_t hi = (uint32_t)__bfloat16_as_ushort(__float2bfloat16(q1));
        w[r] = lo | (hi << 16);
    }
    uint4 st; st.x = w[0]; st.y = w[1]; st.z = w[2]; st.w = w[3];
    ((uint4*)(Q + (size_t)row * NROW))[t] = st;
}

// ------------- bf16 HMMA GEMM: D[M,N] = A[M,K] @ B[N,K]^T -----------------
// Tile: BM=128, BN=128, K-chunk=64 bf16 (128B rows), 3-stage cp.async,
// SW128 swizzle, 8 warps (2x4), warp tile 64x32, m16n8k16 bf16 f32-acc.
// 96KB smem -> 2 CTAs/SM. Epilogue: y = acc * (s_w*m_row) [+ relu^2].
#define BM 128
#define BN 128
#define BKB 128   /* bytes per row per chunk = 64 bf16 */
static constexpr int GEMM_STAGE_BYTES = BM * BKB + BN * BKB;      // 32768
static constexpr int GEMM_SMEM = 3 * GEMM_STAGE_BYTES;            // 98304

template <bool RELUSQ>
__global__ void __launch_bounds__(256, 2) gemm_bf16(
    const __nv_bfloat16* __restrict__ A,
    const __nv_bfloat16* __restrict__ B,
    const float* __restrict__ rowm,
    const float* __restrict__ wscale,
    float* __restrict__ Cout,
    int KDIM, int NOUT) {
    extern __shared__ __align__(1024) char smem[];
    const int tid = threadIdx.x;
    const int wid = tid >> 5;
    const int lane = tid & 31;
    const uint32_t sb = smem_u32(smem);
    const int m0 = blockIdx.y * BM;
    const int n0 = blockIdx.x * BN;

    const char* Ab = (const char*)(A + (size_t)m0 * KDIM);
    const char* Bb = (const char*)(B + (size_t)n0 * KDIM);
    const size_t rowbytes = (size_t)KDIM * 2;
    const int C = KDIM >> 6;                    // chunks of 64 bf16 (128B)

    // per-thread cp.async pattern: 4 chunks A + 4 chunks B per stage
    const int ldr = tid >> 3;                   // 0..31 (base row)
    const int ldc = (tid & 7) * 16;             // 16B chunk within 128B row

    auto load_stage = [&](int c, int st) {
        uint32_t sA = sb + (uint32_t)st * GEMM_STAGE_BYTES;
        uint32_t sB = sA + BM * BKB;
        const char* Ag = Ab + (size_t)c * BKB;
        const char* Bg = Bb + (size_t)c * BKB;
#pragma unroll
        for (int i = 0; i < 4; i++) {
            int r = ldr + i * 32;
            uint32_t so = (uint32_t)(r * BKB + ldc);
            cp_async16(sA + SWZ(so), Ag + (size_t)r * rowbytes + ldc);
        }
#pragma unroll
        for (int i = 0; i < 4; i++) {
            int r = ldr + i * 32;
            uint32_t so = (uint32_t)(r * BKB + ldc);
            cp_async16(sB + SWZ(so), Bg + (size_t)r * rowbytes + ldc);
        }
    };

    // prologue: 2 stages in flight
    load_stage(0, 0); CP_COMMIT();
    load_stage(1, 1); CP_COMMIT();

    // warp tiling: 2 (M) x 4 (N) warps, warp tile 64x32
    const int wm = (wid & 1) * 64;
    const int wn = (wid >> 1) * 32;
    // ldmatrix per-lane quadrant addressing (16 rows x 32 bytes per ldm4)
    const int q = lane >> 3;
    const int row_off = (q & 1) * 8 + (lane & 7);   // 0..15
    const int kb_off = (q >> 1) * 16;               // 0 or 16 bytes

    float acc[4][4][4];
#pragma unroll
    for (int mt = 0; mt < 4; mt++)
#pragma unroll
        for (int nt = 0; nt < 4; nt++)
#pragma unroll
            for (int r = 0; r < 4; r++) acc[mt][nt][r] = 0.f;

    int stc = 0;                                   // stage of chunk c
    for (int c = 0; c < C; c++) {
        CP_WAIT(1);
        __syncthreads();
        int st2 = stc + 2; if (st2 >= 3) st2 -= 3;
        if (c + 2 < C) load_stage(c + 2, st2);
        CP_COMMIT();                               // uniform group accounting

        uint32_t sA = sb + (uint32_t)stc * GEMM_STAGE_BYTES;
        uint32_t sB = sA + BM * BKB;
#pragma unroll
        for (int ks = 0; ks < 4; ks++) {           // 4 x k16 per 128B chunk
            uint32_t afr[4][4];
#pragma unroll
            for (int mt = 0; mt < 4; mt++) {
                uint32_t off = (uint32_t)((wm + mt * 16 + row_off) * BKB +
                                          ks * 32 + kb_off);
                ldm4(afr[mt], sA + SWZ(off));
            }
            uint32_t bfr[2][4];
#pragma unroll
            for (int nh = 0; nh < 2; nh++) {
                uint32_t off = (uint32_t)((wn + nh * 16 + row_off) * BKB +
                                          ks * 32 + kb_off);
                ldm4(bfr[nh], sB + SWZ(off));
            }
#pragma unroll
            for (int mt = 0; mt < 4; mt++)
#pragma unroll
                for (int nt = 0; nt < 4; nt++) {
                    int nh = nt >> 1, sel = nt & 1;
                    mma_bf16(acc[mt][nt], afr[mt], bfr[nh][sel], bfr[nh][sel + 2]);
                }
        }
        __syncthreads();                 // compute done before stage reuse
        if (++stc == 3) stc = 0;
    }

    // ---- epilogue ----
    const float wsv = *wscale;
    const int lr = lane >> 2;            // 0..7
    const int lc = (lane & 3) * 2;
#pragma unroll
    for (int mt = 0; mt < 4; mt++) {
        int r0 = m0 + wm + mt * 16 + lr;
        int r1 = r0 + 8;
        float al0 = wsv * rowm[r0];
        float al1 = wsv * rowm[r1];
        float* o0 = Cout + (size_t)r0 * NOUT + n0 + wn;
        float* o1 = Cout + (size_t)r1 * NOUT + n0 + wn;
#pragma unroll
        for (int nt = 0; nt < 4; nt++) {
            int colb = nt * 8 + lc;
            float y0 = acc[mt][nt][0] * al0;
            float y1 = acc[mt][nt][1] * al0;
            float y2 = acc[mt][nt][2] * al1;
            float y3 = acc[mt][nt][3] * al1;
            if (RELUSQ) {
                y0 = y0 > 0.f ? y0 * y0 : 0.f;
                y1 = y1 > 0.f ? y1 * y1 : 0.f;
                y2 = y2 > 0.f ? y2 * y2 : 0.f;
                y3 = y3 > 0.f ? y3 * y3 : 0.f;
            }
            *(float2*)(o0 + colb) = make_float2(y0, y1);
            *(float2*)(o1 + colb) = make_float2(y2, y3);
        }
    }
}

// -------------------- host entry ------------------------------------------
extern "C" void kernel_launch(void* const* d_in, const int* in_sizes, int n_in,
                              void* d_out, int out_size) {
    const float* x  = (const float*)d_in[0];   // [4,2048,2048]
    const float* wu = (const float*)d_in[1];   // [4096,2048]
    const float* wd = (const float*)d_in[2];   // [2048,4096]
    float* out = (float*)d_out;                // [4,2048,2048]

    void *p_wqu, *p_wqd, *p_xq, *p_h, *p_hq, *p_m1, *p_m2, *p_ws, *p_part;
    cudaGetSymbolAddress(&p_wqu, g_wq_up);
    cudaGetSymbolAddress(&p_wqd, g_wq_dn);
    cudaGetSymbolAddress(&p_xq,  g_xq);
    cudaGetSymbolAddress(&p_h,   g_h);
    cudaGetSymbolAddress(&p_hq,  g_hq);
    cudaGetSymbolAddress(&p_m1,  g_m1);
    cudaGetSymbolAddress(&p_m2,  g_m2);
    cudaGetSymbolAddress(&p_ws,  g_ws);
    cudaGetSymbolAddress(&p_part, g_part);

    cudaFuncSetAttribute(gemm_bf16<true>,
                         cudaFuncAttributeMaxDynamicSharedMemorySize, GEMM_SMEM);
    cudaFuncSetAttribute(gemm_bf16<false>,
                         cudaFuncAttributeMaxDynamicSharedMemorySize, GEMM_SMEM);

    // 1) weight scales (mean|w|, deterministic two-pass)
    wabs_partial<<<dim3(256, 2), 256>>>(wu, wd, (float*)p_part);
    wscale_final<<<2, 256>>>((const float*)p_part, (float*)p_ws);

    // 2) ternary-quantize both weights into bf16 (single launch, grid.y=2)
    wquant_kernel<<<dim3(WN / 256, 2), 256>>>(wu, wd,
        (__nv_bfloat16*)p_wqu, (__nv_bfloat16*)p_wqd, (const float*)p_ws);

    // 3) FWHT(2048) + act quant -> bf16
    fwht_q<HK1, 256><<<MDIM, 256>>>(x, (__nv_bfloat16*)p_xq, (float*)p_m1);

    // 4) GEMM1 (8192x4096x2048) + relu^2 epilogue -> g_h (f32)
    gemm_bf16<true><<<dim3(HK2 / BN, MDIM / BM), 256, GEMM_SMEM>>>(
        (const __nv_bfloat16*)p_xq, (const __nv_bfloat16*)p_wqu,
        (const float*)p_m1, (const float*)p_ws,
        (float*)p_h, HK1, HK2);

    // 5) FWHT(4096) + act quant -> bf16
    fwht_q<HK2, 512><<<MDIM, 512>>>((const float*)p_h, (__nv_bfloat16*)p_hq, (float*)p_m2);

    // 6) GEMM2 (8192x2048x4096) -> out
    gemm_bf16<false><<<dim3(HK1 / BN, MDIM / BM), 256, GEMM_SMEM>>>(
        (const __nv_bfloat16*)p_hq, (const __nv_bfloat16*)p_wqd,
        (const float*)p_m2, (const float*)p_ws + 1,
        out, HK2, HK1);
}